// round 9
// baseline (speedup 1.0000x reference)
#include <cuda_runtime.h>
#include <cuda_bf16.h>
#include <cstddef>

#define Bc 4
#define Hc 8
#define Pc 32
#define Nc 32
#define Dc 16
#define Lc 1024
#define WINc 10
#define NFc 6
#define PREDc 96
#define SEQc 512
#define EPSc 1.1920929e-07f
#define LOG2E 1.4426950408889634f

__device__ float g_h0[Bc * Hc * Lc * Dc];
__device__ float g_h1[Bc * Hc * Lc * Dc];

typedef unsigned long long u64;

__device__ __forceinline__ void ffma2(u64 &d, u64 a, u64 b, u64 c) {
    asm("fma.rn.f32x2 %0, %1, %2, %3;" : "=l"(d) : "l"(a), "l"(b), "l"(c));
}
__device__ __forceinline__ void add2(u64 &d, u64 a, u64 b) {
    asm("add.rn.f32x2 %0, %1, %2;" : "=l"(d) : "l"(a), "l"(b));
}
__device__ __forceinline__ u64 pack2(float lo, float hi) {
    u64 r; asm("mov.b64 %0, {%1, %2};" : "=l"(r) : "f"(lo), "f"(hi)); return r;
}
__device__ __forceinline__ void unpack2(u64 v, float &lo, float &hi) {
    asm("mov.b64 {%0, %1}, %2;" : "=f"(lo), "=f"(hi) : "l"(v));
}
__device__ __forceinline__ float ex2(float x) {
    float r; asm("ex2.approx.f32 %0, %1;" : "=f"(r) : "f"(x)); return r;
}
__device__ __forceinline__ float gelu_exact(float x) {
    return 0.5f * x * (1.0f + erff(x * 0.70710678118654752f));
}

// ---------------------------------------------------------------------------
// Fused layer: signed banded attention + residual + RMSNorm + conv-FFN
// + residual + RMSNorm. Block per (p,h,b); 256 thr = 8 warps; lane = query.
// One-pass softmax (no max-subtraction; |scale*s| fp32-safe). Keys read via
// uniform-broadcast LDG; k-loop unrolled x2 with independent dot/exp chains
// (per-warp key count = npat*4 is even -> no tail).
// ---------------------------------------------------------------------------
__global__ __launch_bounds__(256, 3) void attn_ffn_kernel(
    const float* __restrict__ in, float* __restrict__ out,
    const float* __restrict__ log_scale, const float* __restrict__ attn_nw,
    const float* __restrict__ up_w, const float* __restrict__ down_w,
    const float* __restrict__ ffn_nw)
{
    // part[w][slot][q] : slots 0..15 accp, 16..31 accn, 32 zp, 33 zn
    __shared__ float part[8 * 34 * 32];

    const int p    = blockIdx.x;
    const int hh   = blockIdx.y;
    const int b    = blockIdx.z;
    const int tid  = threadIdx.x;
    const int warp = tid >> 5, lane = tid & 31;

    const float* base = in + ((size_t)(b * Hc + hh) * Lc) * Dc;
    const float* qb   = base + (size_t)p * Nc * Dc;
    const float* kb   = base + (size_t)(p + 1) * Nc * Dc;
    const int npat = min(WINc - 1, (Pc - 1) - p);
    const int nk   = npat * Nc;

    const float scale = fminf(fmaxf(__expf(log_scale[0]), 1.0f), 30.0f) * 0.25f;
    const float c = scale * LOG2E;

    u64 q2[8];
    {
        const float4* q4 = (const float4*)(qb + (size_t)lane * Dc);
        float4 a = q4[0], b4 = q4[1], cc = q4[2], d4 = q4[3];
        q2[0] = pack2(a.x * c,  a.y * c);   q2[1] = pack2(a.z * c,  a.w * c);
        q2[2] = pack2(b4.x * c, b4.y * c);  q2[3] = pack2(b4.z * c, b4.w * c);
        q2[4] = pack2(cc.x * c, cc.y * c);  q2[5] = pack2(cc.z * c, cc.w * c);
        q2[6] = pack2(d4.x * c, d4.y * c);  q2[7] = pack2(d4.z * c, d4.w * c);
    }

    u64 accp2[8], accn2[8];
#pragma unroll
    for (int i = 0; i < 8; i++) { accp2[i] = 0ull; accn2[i] = 0ull; }
    u64 z2 = 0ull;   // (zp, zn)

    // per-warp iteration count nk/8 = npat*4 is even: unroll 2, no tail
    for (int k = warp; k < nk; k += 16) {
        const ulonglong2* krA = (const ulonglong2*)(kb + (size_t)k * Dc);
        const ulonglong2* krB = (const ulonglong2*)(kb + (size_t)(k + 8) * Dc);
        ulonglong2 a0 = krA[0], a1 = krA[1], a2 = krA[2], a3 = krA[3];
        ulonglong2 b0 = krB[0], b1 = krB[1], b2 = krB[2], b3 = krB[3];
        u64 ka[8] = { a0.x, a0.y, a1.x, a1.y, a2.x, a2.y, a3.x, a3.y };
        u64 kbq[8] = { b0.x, b0.y, b1.x, b1.y, b2.x, b2.y, b3.x, b3.y };

        // two independent dot chains
        u64 dA = 0ull, dB = 0ull;
#pragma unroll
        for (int i = 0; i < 8; i++) {
            ffma2(dA, q2[i], ka[i], dA);
            ffma2(dB, q2[i], kbq[i], dB);
        }
        float alo, ahi, blo, bhi;
        unpack2(dA, alo, ahi);
        unpack2(dB, blo, bhi);
        float dotA = alo + ahi, dotB = blo + bhi;
        float epA = ex2(dotA), enA = ex2(-dotA);
        float epB = ex2(dotB), enB = ex2(-dotB);
        add2(z2, z2, pack2(epA + epB, enA + enB));
        u64 epA2 = pack2(epA, epA), enA2 = pack2(enA, enA);
        u64 epB2 = pack2(epB, epB), enB2 = pack2(enB, enB);
#pragma unroll
        for (int i = 0; i < 8; i++) {
            ffma2(accp2[i], ka[i],  epA2, accp2[i]);
            ffma2(accn2[i], ka[i],  enA2, accn2[i]);
            ffma2(accp2[i], kbq[i], epB2, accp2[i]);
            ffma2(accn2[i], kbq[i], enB2, accn2[i]);
        }
    }

    // dump partial state (conflict-free lane-contiguous layout)
    {
        float* pw = part + warp * (34 * 32);
#pragma unroll
        for (int i = 0; i < 8; i++) {
            float l0, h0, l1, h1;
            unpack2(accp2[i], l0, h0);
            pw[(2 * i) * 32 + lane]     = l0;
            pw[(2 * i + 1) * 32 + lane] = h0;
            unpack2(accn2[i], l1, h1);
            pw[(16 + 2 * i) * 32 + lane]     = l1;
            pw[(16 + 2 * i + 1) * 32 + lane] = h1;
        }
        float zp, zn; unpack2(z2, zp, zn);
        pw[32 * 32 + lane] = zp;
        pw[33 * 32 + lane] = zn;
    }
    __syncthreads();

    // merge 8 warps' partials by addition
    for (int i = tid; i < 34 * 32; i += 256) {
        float s = part[i];
#pragma unroll
        for (int w = 1; w < 8; w++) s += part[w * (34 * 32) + i];
        part[i] = s;
    }
    __syncthreads();

    // Finalize: 32 threads, thread = query row.
    if (tid < 32) {
        float x[16];
        if (nk > 0) {
            float izp = 1.0f / part[32 * 32 + tid];
            float izn = 1.0f / part[33 * 32 + tid];
#pragma unroll
            for (int d = 0; d < 16; d++)
                x[d] = part[d * 32 + tid] * izp - part[(16 + d) * 32 + tid] * izn;
        } else {
#pragma unroll
            for (int d = 0; d < 16; d++) x[d] = 0.f;
        }
        const float4* q4 = (const float4*)(qb + (size_t)tid * Dc);
        float4 a = q4[0], b4 = q4[1], cc = q4[2], d4 = q4[3];
        float qq[16] = {a.x,a.y,a.z,a.w,b4.x,b4.y,b4.z,b4.w,
                        cc.x,cc.y,cc.z,cc.w,d4.x,d4.y,d4.z,d4.w};
        float ss = 0.f;
#pragma unroll
        for (int d = 0; d < 16; d++) { x[d] += qq[d]; ss += x[d] * x[d]; }
        float r = rsqrtf(ss * 0.0625f + EPSc);
#pragma unroll
        for (int d = 0; d < 16; d++) x[d] = x[d] * r * attn_nw[d];

        const float u00 = up_w[6*hh+0], u01 = up_w[6*hh+1], u02 = up_w[6*hh+2];
        const float u10 = up_w[6*hh+3], u11 = up_w[6*hh+4], u12 = up_w[6*hh+5];
        const float dw0 = down_w[2*hh+0], dw1 = down_w[2*hh+1];

        float v[16];
        ss = 0.f;
#pragma unroll
        for (int d = 0; d < 16; d++) {
            float xm2 = (d >= 2) ? x[d-2] : 0.f;
            float xm1 = (d >= 1) ? x[d-1] : 0.f;
            float m0 = u00 * xm2 + u01 * xm1 + u02 * x[d];
            float m1 = u10 * xm2 + u11 * xm1 + u12 * x[d];
            float y  = dw0 * gelu_exact(m0) + dw1 * gelu_exact(m1);
            v[d] = x[d] + y;
            ss += v[d] * v[d];
        }
        r = rsqrtf(ss * 0.0625f + EPSc);
        float nv[16];
#pragma unroll
        for (int d = 0; d < 16; d++) nv[d] = v[d] * r * ffn_nw[d];
        float4* orow = (float4*)(out + ((size_t)((b * Hc + hh) * Lc + p * Nc + tid)) * Dc);
        orow[0] = make_float4(nv[0],  nv[1],  nv[2],  nv[3]);
        orow[1] = make_float4(nv[4],  nv[5],  nv[6],  nv[7]);
        orow[2] = make_float4(nv[8],  nv[9],  nv[10], nv[11]);
        orow[3] = make_float4(nv[12], nv[13], nv[14], nv[15]);
    }
}

// ---------------------------------------------------------------------------
__global__ __launch_bounds__(512) void final_copy_kernel(
    const float* __restrict__ hbuf,
    const float* __restrict__ mix_w, const float* __restrict__ mix_b,
    const float* __restrict__ fore_w, const float* __restrict__ fore_b,
    const float* __restrict__ x_original,
    float* __restrict__ out)
{
    const int t = threadIdx.x;
    if (blockIdx.z == 1) {
        int idx = (blockIdx.y * Nc + blockIdx.x) * 512 + t;
        if (idx < (Bc * SEQc * Nc) / 4)
            ((float4*)(out + Bc * PREDc * Nc))[idx] = ((const float4*)x_original)[idx];
        return;
    }

    __shared__ float hm[16 * 32];
    const int n = blockIdx.x, b = blockIdx.y;
    const int d = t >> 5, p = t & 31;

    float acc = mix_b[0];
#pragma unroll
    for (int h = 0; h < Hc; h++)
        acc += hbuf[((size_t)((b * Hc + h) * Lc + p * Nc + n)) * Dc + d] * mix_w[h];
    hm[d * 32 + p] = acc;
    __syncthreads();

    if (t < PREDc) {
        int dd = t / NFc, f = t - dd * NFc;
        float v = fore_b[f];
#pragma unroll
        for (int pp = 0; pp < Pc; pp++)
            v += hm[dd * 32 + pp] * fore_w[f * Pc + pp];
        out[((size_t)b * PREDc + t) * Nc + n] = v;
    }
}

// ---------------------------------------------------------------------------
extern "C" void kernel_launch(void* const* d_in, const int* in_sizes, int n_in,
                              void* d_out, int out_size)
{
    const float* tokens     = (const float*)d_in[0];
    const float* x_original = (const float*)d_in[1];
    const float* log_scales = (const float*)d_in[2];
    const float* attn_norm  = (const float*)d_in[3];
    const float* conv_up    = (const float*)d_in[4];
    const float* conv_down  = (const float*)d_in[5];
    const float* ffn_norm   = (const float*)d_in[6];
    const float* mix_w      = (const float*)d_in[7];
    const float* mix_b      = (const float*)d_in[8];
    const float* fore_w     = (const float*)d_in[9];
    const float* fore_b     = (const float*)d_in[10];
    float* out = (float*)d_out;

    float *h0, *h1;
    cudaGetSymbolAddress((void**)&h0, g_h0);
    cudaGetSymbolAddress((void**)&h1, g_h1);

    dim3 ag(Pc, Hc, Bc);

    attn_ffn_kernel<<<ag, 256>>>(tokens, h0, log_scales + 0, attn_norm + 0,
                                 conv_up + 0, conv_down + 0, ffn_norm + 0);
    attn_ffn_kernel<<<ag, 256>>>(h0, h1, log_scales + 1, attn_norm + Dc,
                                 conv_up + 2*Hc*3, conv_down + Hc*2, ffn_norm + Dc);

    const int fc = Bc * PREDc * Nc;   // 12288
    const int xo = Bc * SEQc * Nc;    // 65536
    dim3 fg(Nc, Bc, (out_size >= fc + xo) ? 2 : 1);
    final_copy_kernel<<<fg, 512>>>(h1, mix_w, mix_b, fore_w, fore_b, x_original, out);
}

// round 11
// speedup vs baseline: 2.0957x; 2.0957x over previous
#include <cuda_runtime.h>
#include <cuda_bf16.h>
#include <cstddef>

#define Bc 4
#define Hc 8
#define Pc 32
#define Nc 32
#define Dc 16
#define Lc 1024
#define WINc 10
#define NFc 6
#define PREDc 96
#define SEQc 512
#define EPSc 1.1920929e-07f
#define LOG2E 1.4426950408889634f

__device__ float g_h0[Bc * Hc * Lc * Dc];
__device__ float g_h1[Bc * Hc * Lc * Dc];

typedef unsigned long long u64;

__device__ __forceinline__ void ffma2(u64 &d, u64 a, u64 b, u64 c) {
    asm("fma.rn.f32x2 %0, %1, %2, %3;" : "=l"(d) : "l"(a), "l"(b), "l"(c));
}
__device__ __forceinline__ void add2(u64 &d, u64 a, u64 b) {
    asm("add.rn.f32x2 %0, %1, %2;" : "=l"(d) : "l"(a), "l"(b));
}
__device__ __forceinline__ u64 pack2(float lo, float hi) {
    u64 r; asm("mov.b64 %0, {%1, %2};" : "=l"(r) : "f"(lo), "f"(hi)); return r;
}
__device__ __forceinline__ void unpack2(u64 v, float &lo, float &hi) {
    asm("mov.b64 {%0, %1}, %2;" : "=f"(lo), "=f"(hi) : "l"(v));
}
__device__ __forceinline__ float ex2(float x) {
    float r; asm("ex2.approx.f32 %0, %1;" : "=f"(r) : "f"(x)); return r;
}
__device__ __forceinline__ float gelu_exact(float x) {
    return 0.5f * x * (1.0f + erff(x * 0.70710678118654752f));
}

// ---------------------------------------------------------------------------
// Fused layer: signed banded attention + residual + RMSNorm + conv-FFN
// + residual + RMSNorm. Block per (p,h,b); 256 thr = 8 warps; lane = query.
// One-pass softmax (no max-subtraction; |scale*s| fp32-safe). Keys read via
// uniform-broadcast LDG; k-loop unrolled x2 with independent half-split dot
// chains. NO occupancy cap: ptxas must keep the full live set in registers
// (spilling at a forced 80-reg cap is what sank the previous attempt).
// ---------------------------------------------------------------------------
__global__ __launch_bounds__(256) void attn_ffn_kernel(
    const float* __restrict__ in, float* __restrict__ out,
    const float* __restrict__ log_scale, const float* __restrict__ attn_nw,
    const float* __restrict__ up_w, const float* __restrict__ down_w,
    const float* __restrict__ ffn_nw)
{
    // part[w][slot][q] : slots 0..15 accp, 16..31 accn, 32 zp, 33 zn
    __shared__ float part[8 * 34 * 32];

    const int p    = blockIdx.x;
    const int hh   = blockIdx.y;
    const int b    = blockIdx.z;
    const int tid  = threadIdx.x;
    const int warp = tid >> 5, lane = tid & 31;

    const float* base = in + ((size_t)(b * Hc + hh) * Lc) * Dc;
    const float* qb   = base + (size_t)p * Nc * Dc;
    const float* kb   = base + (size_t)(p + 1) * Nc * Dc;
    const int npat = min(WINc - 1, (Pc - 1) - p);
    const int nk   = npat * Nc;

    const float scale = fminf(fmaxf(__expf(log_scale[0]), 1.0f), 30.0f) * 0.25f;
    const float c = scale * LOG2E;

    u64 q2[8];
    {
        const float4* q4 = (const float4*)(qb + (size_t)lane * Dc);
        float4 a = q4[0], b4 = q4[1], cc = q4[2], d4 = q4[3];
        q2[0] = pack2(a.x * c,  a.y * c);   q2[1] = pack2(a.z * c,  a.w * c);
        q2[2] = pack2(b4.x * c, b4.y * c);  q2[3] = pack2(b4.z * c, b4.w * c);
        q2[4] = pack2(cc.x * c, cc.y * c);  q2[5] = pack2(cc.z * c, cc.w * c);
        q2[6] = pack2(d4.x * c, d4.y * c);  q2[7] = pack2(d4.z * c, d4.w * c);
    }

    u64 accp2[8], accn2[8];
#pragma unroll
    for (int i = 0; i < 8; i++) { accp2[i] = 0ull; accn2[i] = 0ull; }
    u64 z2 = 0ull;   // (zp, zn)

    // per-warp iteration count nk/8 = npat*4 is even: unroll 2, no tail
    for (int k = warp; k < nk; k += 16) {
        const ulonglong2* krA = (const ulonglong2*)(kb + (size_t)k * Dc);
        const ulonglong2* krB = (const ulonglong2*)(kb + (size_t)(k + 8) * Dc);
        ulonglong2 a0 = krA[0], a1 = krA[1], a2 = krA[2], a3 = krA[3];
        ulonglong2 b0 = krB[0], b1 = krB[1], b2 = krB[2], b3 = krB[3];
        u64 ka[8] = { a0.x, a0.y, a1.x, a1.y, a2.x, a2.y, a3.x, a3.y };
        u64 kbq[8] = { b0.x, b0.y, b1.x, b1.y, b2.x, b2.y, b3.x, b3.y };

        // four independent half-dot chains (4 deep each)
        u64 dA0 = 0ull, dA1 = 0ull, dB0 = 0ull, dB1 = 0ull;
#pragma unroll
        for (int i = 0; i < 4; i++) {
            ffma2(dA0, q2[i],     ka[i],      dA0);
            ffma2(dA1, q2[i + 4], ka[i + 4],  dA1);
            ffma2(dB0, q2[i],     kbq[i],     dB0);
            ffma2(dB1, q2[i + 4], kbq[i + 4], dB1);
        }
        add2(dA0, dA0, dA1);
        add2(dB0, dB0, dB1);
        float alo, ahi, blo, bhi;
        unpack2(dA0, alo, ahi);
        unpack2(dB0, blo, bhi);
        float dotA = alo + ahi, dotB = blo + bhi;
        float epA = ex2(dotA), enA = ex2(-dotA);
        float epB = ex2(dotB), enB = ex2(-dotB);
        add2(z2, z2, pack2(epA + epB, enA + enB));
        u64 epA2 = pack2(epA, epA), enA2 = pack2(enA, enA);
        u64 epB2 = pack2(epB, epB), enB2 = pack2(enB, enB);
#pragma unroll
        for (int i = 0; i < 8; i++) {
            ffma2(accp2[i], ka[i],  epA2, accp2[i]);
            ffma2(accn2[i], ka[i],  enA2, accn2[i]);
            ffma2(accp2[i], kbq[i], epB2, accp2[i]);
            ffma2(accn2[i], kbq[i], enB2, accn2[i]);
        }
    }

    // dump partial state (conflict-free lane-contiguous layout)
    {
        float* pw = part + warp * (34 * 32);
#pragma unroll
        for (int i = 0; i < 8; i++) {
            float l0, h0, l1, h1;
            unpack2(accp2[i], l0, h0);
            pw[(2 * i) * 32 + lane]     = l0;
            pw[(2 * i + 1) * 32 + lane] = h0;
            unpack2(accn2[i], l1, h1);
            pw[(16 + 2 * i) * 32 + lane]     = l1;
            pw[(16 + 2 * i + 1) * 32 + lane] = h1;
        }
        float zp, zn; unpack2(z2, zp, zn);
        pw[32 * 32 + lane] = zp;
        pw[33 * 32 + lane] = zn;
    }
    __syncthreads();

    // merge 8 warps' partials by addition
    for (int i = tid; i < 34 * 32; i += 256) {
        float s = part[i];
#pragma unroll
        for (int w = 1; w < 8; w++) s += part[w * (34 * 32) + i];
        part[i] = s;
    }
    __syncthreads();

    // Finalize: 32 threads, thread = query row.
    if (tid < 32) {
        float x[16];
        if (nk > 0) {
            float izp = 1.0f / part[32 * 32 + tid];
            float izn = 1.0f / part[33 * 32 + tid];
#pragma unroll
            for (int d = 0; d < 16; d++)
                x[d] = part[d * 32 + tid] * izp - part[(16 + d) * 32 + tid] * izn;
        } else {
#pragma unroll
            for (int d = 0; d < 16; d++) x[d] = 0.f;
        }
        const float4* q4 = (const float4*)(qb + (size_t)tid * Dc);
        float4 a = q4[0], b4 = q4[1], cc = q4[2], d4 = q4[3];
        float qq[16] = {a.x,a.y,a.z,a.w,b4.x,b4.y,b4.z,b4.w,
                        cc.x,cc.y,cc.z,cc.w,d4.x,d4.y,d4.z,d4.w};
        float ss = 0.f;
#pragma unroll
        for (int d = 0; d < 16; d++) { x[d] += qq[d]; ss += x[d] * x[d]; }
        float r = rsqrtf(ss * 0.0625f + EPSc);
#pragma unroll
        for (int d = 0; d < 16; d++) x[d] = x[d] * r * attn_nw[d];

        const float u00 = up_w[6*hh+0], u01 = up_w[6*hh+1], u02 = up_w[6*hh+2];
        const float u10 = up_w[6*hh+3], u11 = up_w[6*hh+4], u12 = up_w[6*hh+5];
        const float dw0 = down_w[2*hh+0], dw1 = down_w[2*hh+1];

        float v[16];
        ss = 0.f;
#pragma unroll
        for (int d = 0; d < 16; d++) {
            float xm2 = (d >= 2) ? x[d-2] : 0.f;
            float xm1 = (d >= 1) ? x[d-1] : 0.f;
            float m0 = u00 * xm2 + u01 * xm1 + u02 * x[d];
            float m1 = u10 * xm2 + u11 * xm1 + u12 * x[d];
            float y  = dw0 * gelu_exact(m0) + dw1 * gelu_exact(m1);
            v[d] = x[d] + y;
            ss += v[d] * v[d];
        }
        r = rsqrtf(ss * 0.0625f + EPSc);
        float nv[16];
#pragma unroll
        for (int d = 0; d < 16; d++) nv[d] = v[d] * r * ffn_nw[d];
        float4* orow = (float4*)(out + ((size_t)((b * Hc + hh) * Lc + p * Nc + tid)) * Dc);
        orow[0] = make_float4(nv[0],  nv[1],  nv[2],  nv[3]);
        orow[1] = make_float4(nv[4],  nv[5],  nv[6],  nv[7]);
        orow[2] = make_float4(nv[8],  nv[9],  nv[10], nv[11]);
        orow[3] = make_float4(nv[12], nv[13], nv[14], nv[15]);
    }
}

// ---------------------------------------------------------------------------
__global__ __launch_bounds__(512) void final_copy_kernel(
    const float* __restrict__ hbuf,
    const float* __restrict__ mix_w, const float* __restrict__ mix_b,
    const float* __restrict__ fore_w, const float* __restrict__ fore_b,
    const float* __restrict__ x_original,
    float* __restrict__ out)
{
    const int t = threadIdx.x;
    if (blockIdx.z == 1) {
        int idx = (blockIdx.y * Nc + blockIdx.x) * 512 + t;
        if (idx < (Bc * SEQc * Nc) / 4)
            ((float4*)(out + Bc * PREDc * Nc))[idx] = ((const float4*)x_original)[idx];
        return;
    }

    __shared__ float hm[16 * 32];
    const int n = blockIdx.x, b = blockIdx.y;
    const int d = t >> 5, p = t & 31;

    float acc = mix_b[0];
#pragma unroll
    for (int h = 0; h < Hc; h++)
        acc += hbuf[((size_t)((b * Hc + h) * Lc + p * Nc + n)) * Dc + d] * mix_w[h];
    hm[d * 32 + p] = acc;
    __syncthreads();

    if (t < PREDc) {
        int dd = t / NFc, f = t - dd * NFc;
        float v = fore_b[f];
#pragma unroll
        for (int pp = 0; pp < Pc; pp++)
            v += hm[dd * 32 + pp] * fore_w[f * Pc + pp];
        out[((size_t)b * PREDc + t) * Nc + n] = v;
    }
}

// ---------------------------------------------------------------------------
extern "C" void kernel_launch(void* const* d_in, const int* in_sizes, int n_in,
                              void* d_out, int out_size)
{
    const float* tokens     = (const float*)d_in[0];
    const float* x_original = (const float*)d_in[1];
    const float* log_scales = (const float*)d_in[2];
    const float* attn_norm  = (const float*)d_in[3];
    const float* conv_up    = (const float*)d_in[4];
    const float* conv_down  = (const float*)d_in[5];
    const float* ffn_norm   = (const float*)d_in[6];
    const float* mix_w      = (const float*)d_in[7];
    const float* mix_b      = (const float*)d_in[8];
    const float* fore_w     = (const float*)d_in[9];
    const float* fore_b     = (const float*)d_in[10];
    float* out = (float*)d_out;

    float *h0, *h1;
    cudaGetSymbolAddress((void**)&h0, g_h0);
    cudaGetSymbolAddress((void**)&h1, g_h1);

    dim3 ag(Pc, Hc, Bc);

    attn_ffn_kernel<<<ag, 256>>>(tokens, h0, log_scales + 0, attn_norm + 0,
                                 conv_up + 0, conv_down + 0, ffn_norm + 0);
    attn_ffn_kernel<<<ag, 256>>>(h0, h1, log_scales + 1, attn_norm + Dc,
                                 conv_up + 2*Hc*3, conv_down + Hc*2, ffn_norm + Dc);

    const int fc = Bc * PREDc * Nc;   // 12288
    const int xo = Bc * SEQc * Nc;    // 65536
    dim3 fg(Nc, Bc, (out_size >= fc + xo) ? 2 : 1);
    final_copy_kernel<<<fg, 512>>>(h1, mix_w, mix_b, fore_w, fore_b, x_original, out);
}